// round 1
// baseline (speedup 1.0000x reference)
#include <cuda_runtime.h>

#define B_DIM 8192
#define S_DIM 256
#define R_DIM 8192

// Scratch (device globals are the allowed scratch mechanism; no allocations).
__device__ float g_flux[(size_t)B_DIM * R_DIM];  // 256 MB
__device__ float g_logT[B_DIM];
__device__ float g_invT[B_DIM];
__device__ float g_expg[R_DIM];   // exp(-gamma[r])

// ---------------------------------------------------------------------------
// Kernel 0: per-b and per-r precomputation (B == R == 8192 here)
// ---------------------------------------------------------------------------
__global__ void precompute_kernel(const float* __restrict__ temperature,
                                  const float* __restrict__ gamma)
{
    int i = blockIdx.x * blockDim.x + threadIdx.x;
    if (i < B_DIM) {
        float T = temperature[i];
        g_logT[i] = logf(T * (1.0f / 300.0f));
        g_invT[i] = 1.0f / T;
    }
    if (i < R_DIM) {
        g_expg[i] = expf(-gamma[i]);
    }
}

// ---------------------------------------------------------------------------
// Kernel 1: flux[b,r] = rate(b,r) * ab_pad[b, rm0[r]] * ab_pad[b, rm1[r]]
// One thread per r, looping over 32 consecutive b. Per-r params cached in
// registers; abundance row is 1 KB -> L1 resident per b.
// ---------------------------------------------------------------------------
__global__ __launch_bounds__(256)
void flux_kernel(const float* __restrict__ abundances,
                 const float* __restrict__ cr_rate,
                 const float* __restrict__ fuv_rate,
                 const float* __restrict__ alpha,
                 const float* __restrict__ beta,
                 const float* __restrict__ gamma,
                 const int*   __restrict__ rm,
                 const int*   __restrict__ rtype)
{
    int r  = blockIdx.x * 256 + threadIdx.x;
    int b0 = blockIdx.y * 32;

    float al = alpha[r];
    float be = beta[r];
    float ga = gamma[r];
    int   rt = rtype[r];
    int   m0 = rm[2 * r];
    int   m1 = rm[2 * r + 1];
    float eg = g_expg[r];

    #pragma unroll 4
    for (int bb = 0; bb < 32; ++bb) {
        int b = b0 + bb;
        float k;
        if (rt == 0) {
            k = al * __expf(fmaf(be, g_logT[b], -ga * g_invT[b]));
        } else if (rt == 1) {
            k = al * cr_rate[b];
        } else {
            k = al * eg * fuv_rate[b];
        }
        const float* abrow = abundances + (size_t)b * S_DIM;
        float a0 = (m0 < S_DIM) ? abrow[m0] : 1.0f;
        float a1 = (m1 < S_DIM) ? abrow[m1] : 1.0f;
        g_flux[(size_t)b * R_DIM + r] = k * a0 * a1;
    }
}

// ---------------------------------------------------------------------------
// Kernel 2: out[b,s] = sum_r flux[b,r] * inc[s,r]
// Classic 128x128x8 SGEMM, 256 threads, 8x8 per-thread microtile.
// Both operands are K(=r)-contiguous -> inner-product GEMM with transpose
// on smem store.
// ---------------------------------------------------------------------------
__global__ __launch_bounds__(256)
void gemm_kernel(const float* __restrict__ inc,   // [S, R]
                 float* __restrict__ out)          // [B, S]
{
    __shared__ float As[8][128];  // As[k][m]  (m = b within tile)
    __shared__ float Bs[8][128];  // Bs[k][n]  (n = s within tile)

    const int bn = blockIdx.x * 128;  // s tile offset
    const int bm = blockIdx.y * 128;  // b tile offset
    const int tid = threadIdx.x;

    // Global->smem loader mapping: each thread loads one float4 of A and one of B.
    const int lrow = tid >> 1;          // 0..127
    const int lk   = (tid & 1) * 4;     // 0 or 4

    // Microtile mapping
    const int tx = tid & 15;            // 0..15 (s)
    const int ty = tid >> 4;            // 0..15 (b)

    const float* aptr = g_flux + (size_t)(bm + lrow) * R_DIM + lk;
    const float* bptr = inc    + (size_t)(bn + lrow) * R_DIM + lk;

    float acc[8][8];
    #pragma unroll
    for (int i = 0; i < 8; ++i)
        #pragma unroll
        for (int j = 0; j < 8; ++j)
            acc[i][j] = 0.0f;

    for (int k0 = 0; k0 < R_DIM; k0 += 8) {
        float4 av = *(const float4*)(aptr + k0);
        float4 bv = *(const float4*)(bptr + k0);

        __syncthreads();  // previous iteration's compute must be done
        As[lk + 0][lrow] = av.x;
        As[lk + 1][lrow] = av.y;
        As[lk + 2][lrow] = av.z;
        As[lk + 3][lrow] = av.w;
        Bs[lk + 0][lrow] = bv.x;
        Bs[lk + 1][lrow] = bv.y;
        Bs[lk + 2][lrow] = bv.z;
        Bs[lk + 3][lrow] = bv.w;
        __syncthreads();

        #pragma unroll
        for (int k = 0; k < 8; ++k) {
            float a[8], bb[8];
            #pragma unroll
            for (int i = 0; i < 4; ++i) {
                a[i]      = As[k][ty * 8 + i];
                a[i + 4]  = As[k][ty * 8 + 4 + i];
                bb[i]     = Bs[k][tx * 8 + i];
                bb[i + 4] = Bs[k][tx * 8 + 4 + i];
            }
            #pragma unroll
            for (int i = 0; i < 8; ++i)
                #pragma unroll
                for (int j = 0; j < 8; ++j)
                    acc[i][j] = fmaf(a[i], bb[j], acc[i][j]);
        }
    }

    // Epilogue: vectorized stores
    #pragma unroll
    for (int i = 0; i < 8; ++i) {
        int row = bm + ty * 8 + i;
        float* orow = out + (size_t)row * S_DIM + bn + tx * 8;
        float4 v0 = make_float4(acc[i][0], acc[i][1], acc[i][2], acc[i][3]);
        float4 v1 = make_float4(acc[i][4], acc[i][5], acc[i][6], acc[i][7]);
        *(float4*)(orow)     = v0;
        *(float4*)(orow + 4) = v1;
    }
}

// ---------------------------------------------------------------------------
// Input order (metadata): 0 time, 1 abundances, 2 temperature, 3 cr_rate,
// 4 fuv_rate, 5 incidence, 6 alpha, 7 beta, 8 gamma,
// 9 reactant_multipliers (int32 [R,2]), 10 rtype (int32 [R])
// ---------------------------------------------------------------------------
extern "C" void kernel_launch(void* const* d_in, const int* in_sizes, int n_in,
                              void* d_out, int out_size)
{
    const float* abundances  = (const float*)d_in[1];
    const float* temperature = (const float*)d_in[2];
    const float* cr_rate     = (const float*)d_in[3];
    const float* fuv_rate    = (const float*)d_in[4];
    const float* incidence   = (const float*)d_in[5];
    const float* alpha       = (const float*)d_in[6];
    const float* beta        = (const float*)d_in[7];
    const float* gamma       = (const float*)d_in[8];
    const int*   rm          = (const int*)d_in[9];
    const int*   rtype       = (const int*)d_in[10];
    float*       out         = (float*)d_out;

    precompute_kernel<<<(B_DIM + 255) / 256, 256>>>(temperature, gamma);

    flux_kernel<<<dim3(R_DIM / 256, B_DIM / 32), 256>>>(
        abundances, cr_rate, fuv_rate, alpha, beta, gamma, rm, rtype);

    gemm_kernel<<<dim3(S_DIM / 128, B_DIM / 128), 256>>>(incidence, out);
}

// round 4
// speedup vs baseline: 2.6204x; 2.6204x over previous
#include <cuda_runtime.h>
#include <cuda_bf16.h>
#include <cstdint>

#define B_DIM 8192
#define S_DIM 256
#define R_DIM 8192

// ---------------------------------------------------------------------------
// Device-global scratch (allocation-free rule)
// ---------------------------------------------------------------------------
__device__ __nv_bfloat16 g_fhi[(size_t)B_DIM * R_DIM];  // 128 MB
__device__ __nv_bfloat16 g_flo[(size_t)B_DIM * R_DIM];  // 128 MB
__device__ __nv_bfloat16 g_ihi[(size_t)S_DIM * R_DIM];  // 4 MB
__device__ __nv_bfloat16 g_ilo[(size_t)S_DIM * R_DIM];  // 4 MB
__device__ float g_logT[B_DIM];
__device__ float g_invT[B_DIM];
__device__ float g_expg[R_DIM];

// ---------------------------------------------------------------------------
// PTX helpers (compute_103-portable only: mma.sync / ldmatrix / cp.async)
// ---------------------------------------------------------------------------
__device__ __forceinline__ uint32_t s2u(const void* p) {
    uint32_t a;
    asm("{ .reg .u64 t; cvta.to.shared.u64 t, %1; cvt.u32.u64 %0, t; }"
        : "=r"(a) : "l"(p));
    return a;
}

#define LDSM4(r, addr)                                                         \
    asm volatile("ldmatrix.sync.aligned.m8n8.x4.shared.b16 {%0,%1,%2,%3}, [%4];" \
                 : "=r"((r)[0]), "=r"((r)[1]), "=r"((r)[2]), "=r"((r)[3])      \
                 : "r"(addr))

#define MMA16816(c, a, b0, b1)                                                 \
    asm volatile("mma.sync.aligned.m16n8k16.row.col.f32.bf16.bf16.f32 "        \
                 "{%0,%1,%2,%3}, {%4,%5,%6,%7}, {%8,%9}, {%0,%1,%2,%3};"       \
                 : "+f"((c)[0]), "+f"((c)[1]), "+f"((c)[2]), "+f"((c)[3])      \
                 : "r"((a)[0]), "r"((a)[1]), "r"((a)[2]), "r"((a)[3]),         \
                   "r"(b0), "r"(b1))

#define CP16(saddr, gptr)                                                      \
    asm volatile("cp.async.cg.shared.global [%0], [%1], 16;"                   \
                 :: "r"(saddr), "l"(gptr))

#define CP_COMMIT() asm volatile("cp.async.commit_group;" ::: "memory")
#define CP_WAIT1()  asm volatile("cp.async.wait_group 1;" ::: "memory")

// ---------------------------------------------------------------------------
// Kernel 0: per-b and per-r precomputation
// ---------------------------------------------------------------------------
__global__ void precompute_kernel(const float* __restrict__ temperature,
                                  const float* __restrict__ gamma)
{
    int i = blockIdx.x * blockDim.x + threadIdx.x;
    if (i < B_DIM) {
        float T = temperature[i];
        g_logT[i] = logf(T * (1.0f / 300.0f));
        g_invT[i] = 1.0f / T;
    }
    if (i < R_DIM) {
        g_expg[i] = expf(-gamma[i]);
    }
}

// ---------------------------------------------------------------------------
// Kernel 0b: split incidence [S, R] into bf16 hi/lo
// ---------------------------------------------------------------------------
__global__ __launch_bounds__(256)
void split_inc_kernel(const float* __restrict__ inc)
{
    size_t i = (size_t)blockIdx.x * 256 + threadIdx.x;
    float v = inc[i];
    __nv_bfloat16 h = __float2bfloat16(v);
    g_ihi[i] = h;
    g_ilo[i] = __float2bfloat16(v - __bfloat162float(h));
}

// ---------------------------------------------------------------------------
// Kernel 1: flux -> bf16 hi/lo split
// ---------------------------------------------------------------------------
__global__ __launch_bounds__(256)
void flux_kernel(const float* __restrict__ abundances,
                 const float* __restrict__ cr_rate,
                 const float* __restrict__ fuv_rate,
                 const float* __restrict__ alpha,
                 const float* __restrict__ beta,
                 const float* __restrict__ gamma,
                 const int*   __restrict__ rm,
                 const int*   __restrict__ rtype)
{
    int r  = blockIdx.x * 256 + threadIdx.x;
    int b0 = blockIdx.y * 32;

    float al = alpha[r];
    float be = beta[r];
    float ga = gamma[r];
    int   rt = rtype[r];
    int   m0 = rm[2 * r];
    int   m1 = rm[2 * r + 1];
    float eg = g_expg[r];

    #pragma unroll 4
    for (int bb = 0; bb < 32; ++bb) {
        int b = b0 + bb;
        float k;
        if (rt == 0) {
            k = al * __expf(fmaf(be, g_logT[b], -ga * g_invT[b]));
        } else if (rt == 1) {
            k = al * cr_rate[b];
        } else {
            k = al * eg * fuv_rate[b];
        }
        const float* abrow = abundances + (size_t)b * S_DIM;
        float a0 = (m0 < S_DIM) ? abrow[m0] : 1.0f;
        float a1 = (m1 < S_DIM) ? abrow[m1] : 1.0f;
        float v = k * a0 * a1;
        __nv_bfloat16 h = __float2bfloat16(v);
        size_t idx = (size_t)b * R_DIM + r;
        g_fhi[idx] = h;
        g_flo[idx] = __float2bfloat16(v - __bfloat162float(h));
    }
}

// ---------------------------------------------------------------------------
// Kernel 2: mma.sync bf16 GEMM.  out[b,s] = sum_r flux[b,r]*inc[s,r]
// Split-product: fh*ih + fh*il + fl*ih, fp32 accumulators in registers.
// CTA tile M=128(b) x N=128(s), BK=32. 8 warps in 4(m) x 2(n); warp tile 32x64.
// cp.async double-buffered smem; 80B-padded rows -> conflict-free ldmatrix.
// ---------------------------------------------------------------------------
#define BK 32
#define ROW_BYTES 80                        // 64B data + 16B pad (bank rotation)
#define TILE_BYTES (128 * ROW_BYTES)        // 10240
#define STAGE_BYTES (4 * TILE_BYTES)        // Ahi, Alo, Bhi, Blo = 40960
#define SMEM_BYTES (2 * STAGE_BYTES)        // 81920
#define OFF_AHI 0
#define OFF_ALO TILE_BYTES
#define OFF_BHI (2 * TILE_BYTES)
#define OFF_BLO (3 * TILE_BYTES)
#define NUM_KTILES (R_DIM / BK)             // 256

__device__ __forceinline__ void prefetch_stage(uint32_t sb, int stoff,
                                               int bm, int bn, int k0, int tid)
{
    #pragma unroll
    for (int i = 0; i < 2; ++i) {
        int idx = i * 256 + tid;            // 0..511
        int row = idx >> 2;                 // 0..127
        int c   = idx & 3;                  // 16B chunk in 64B row
        uint32_t so = (uint32_t)(stoff + row * ROW_BYTES + c * 16);
        size_t ga = (size_t)(bm + row) * R_DIM + k0 + c * 8;
        size_t gb = (size_t)(bn + row) * R_DIM + k0 + c * 8;
        CP16(sb + so + OFF_AHI, g_fhi + ga);
        CP16(sb + so + OFF_ALO, g_flo + ga);
        CP16(sb + so + OFF_BHI, g_ihi + gb);
        CP16(sb + so + OFF_BLO, g_ilo + gb);
    }
}

__global__ __launch_bounds__(256)
void gemm_kernel(float* __restrict__ out)
{
    extern __shared__ char smbuf[];
    const uint32_t sb = s2u(smbuf);
    const int tid  = threadIdx.x;
    const int wid  = tid >> 5;
    const int lane = tid & 31;

    const int bn = blockIdx.x * 128;        // s tile
    const int bm = blockIdx.y * 128;        // b tile
    const int wm = (wid >> 1) * 32;         // warp m offset in tile
    const int wn = (wid & 1) * 64;          // warp n offset in tile

    float acc[2][8][4];
    #pragma unroll
    for (int i = 0; i < 2; ++i)
        #pragma unroll
        for (int j = 0; j < 8; ++j)
            #pragma unroll
            for (int q = 0; q < 4; ++q)
                acc[i][j][q] = 0.0f;

    prefetch_stage(sb, 0, bm, bn, 0, tid);
    CP_COMMIT();
    prefetch_stage(sb, STAGE_BYTES, bm, bn, BK, tid);
    CP_COMMIT();

    // ldmatrix lane-address components (constant across loop)
    const int a_row = (lane & 15);                        // within m16 tile
    const int a_koff = (lane >> 4) << 3;                  // 0 or 8
    const int b_row = (lane & 7) + ((lane >> 4) << 3);    // within n16 group
    const int b_koff = (lane & 8);                        // 0 or 8

    for (int t = 0; t < NUM_KTILES; ++t) {
        CP_WAIT1();
        __syncthreads();
        const int stoff = (t & 1) * STAGE_BYTES;

        #pragma unroll
        for (int kk = 0; kk < BK; kk += 16) {
            uint32_t ah[2][4], al[2][4];
            #pragma unroll
            for (int i = 0; i < 2; ++i) {
                uint32_t ar = sb + stoff +
                    (uint32_t)((wm + i * 16 + a_row) * ROW_BYTES + (kk + a_koff) * 2);
                LDSM4(ah[i], ar + OFF_AHI);
                LDSM4(al[i], ar + OFF_ALO);
            }
            #pragma unroll
            for (int j = 0; j < 4; ++j) {   // n16 groups -> n8 tiles 2j, 2j+1
                uint32_t br = sb + stoff +
                    (uint32_t)((wn + j * 16 + b_row) * ROW_BYTES + (kk + b_koff) * 2);
                uint32_t bh[4], bl[4];
                LDSM4(bh, br + OFF_BHI);
                LDSM4(bl, br + OFF_BLO);
                #pragma unroll
                for (int i = 0; i < 2; ++i) {
                    MMA16816(acc[i][2 * j],     ah[i], bh[0], bh[1]);
                    MMA16816(acc[i][2 * j],     ah[i], bl[0], bl[1]);
                    MMA16816(acc[i][2 * j],     al[i], bh[0], bh[1]);
                    MMA16816(acc[i][2 * j + 1], ah[i], bh[2], bh[3]);
                    MMA16816(acc[i][2 * j + 1], ah[i], bl[2], bl[3]);
                    MMA16816(acc[i][2 * j + 1], al[i], bh[2], bh[3]);
                }
            }
        }

        __syncthreads();
        if (t + 2 < NUM_KTILES) {
            prefetch_stage(sb, (t & 1) * STAGE_BYTES, bm, bn, (t + 2) * BK, tid);
        }
        CP_COMMIT();
    }

    // Epilogue: c0,c1 -> (g, 2c..2c+1); c2,c3 -> (g+8, 2c..2c+1)
    const int eg = lane >> 2;
    const int ec = (lane & 3) * 2;
    #pragma unroll
    for (int i = 0; i < 2; ++i) {
        #pragma unroll
        for (int j = 0; j < 8; ++j) {
            int row = bm + wm + i * 16 + eg;
            int col = bn + wn + j * 8 + ec;
            float* p = out + (size_t)row * S_DIM + col;
            *(float2*)p = make_float2(acc[i][j][0], acc[i][j][1]);
            *(float2*)(p + 8 * S_DIM) = make_float2(acc[i][j][2], acc[i][j][3]);
        }
    }
}

// ---------------------------------------------------------------------------
// Input order: 0 time, 1 abundances, 2 temperature, 3 cr_rate, 4 fuv_rate,
// 5 incidence, 6 alpha, 7 beta, 8 gamma, 9 reactant_multipliers, 10 rtype
// ---------------------------------------------------------------------------
extern "C" void kernel_launch(void* const* d_in, const int* in_sizes, int n_in,
                              void* d_out, int out_size)
{
    const float* abundances  = (const float*)d_in[1];
    const float* temperature = (const float*)d_in[2];
    const float* cr_rate     = (const float*)d_in[3];
    const float* fuv_rate    = (const float*)d_in[4];
    const float* incidence   = (const float*)d_in[5];
    const float* alpha       = (const float*)d_in[6];
    const float* beta        = (const float*)d_in[7];
    const float* gamma       = (const float*)d_in[8];
    const int*   rm          = (const int*)d_in[9];
    const int*   rtype       = (const int*)d_in[10];
    float*       out         = (float*)d_out;

    cudaFuncSetAttribute(gemm_kernel,
                         cudaFuncAttributeMaxDynamicSharedMemorySize, SMEM_BYTES);

    precompute_kernel<<<(B_DIM + 255) / 256, 256>>>(temperature, gamma);

    split_inc_kernel<<<(S_DIM * R_DIM) / 256, 256>>>(incidence);

    flux_kernel<<<dim3(R_DIM / 256, B_DIM / 32), 256>>>(
        abundances, cr_rate, fuv_rate, alpha, beta, gamma, rm, rtype);

    gemm_kernel<<<dim3(S_DIM / 128, B_DIM / 128), 256, SMEM_BYTES>>>(out);
}